// round 9
// baseline (speedup 1.0000x reference)
#include <cuda_runtime.h>
#include <cuda_bf16.h>
#include <stdint.h>

// WeightsDropout: per row of [8192,1,4096] f32, zero the 2048 smallest
// (stable-argsort tie-break by index), softmax over survivors.
//
// One CTA (256 thr) per row, 16 elems/thread in registers, 5 CTAs/SM.
// No max pass (vals in (0,1): exp never overflows; softmax shift-invariant).
// Pass 1 builds a 1024-bin count histogram over [0.46875, 0.53125) AND
// fixed-point (x2^26) uint64 per-bin exp sums + above-window exp partials,
// so the denominator falls out of the histogram scan -- no second
// reduction. rstar==0 (P~0.89): keep = bin >= bstar, 3 barriers total.
// rstar>0: gather boundary keys (bits<<12|idx == stable order), rank once.
// Window miss / overflow: exact radix-select fallback (cold).
// All cross-thread sums are integer atomics or fixed-tree -> deterministic.

namespace {

constexpr int N       = 4096;
constexpr int KDROP   = 2048;
constexpr int THREADS = 256;
constexpr int VEC     = 4;                // float4 per thread (16 elems)
constexpr int NWARP   = THREADS / 32;     // 8
constexpr int NB      = 1024;
constexpr int C2_CAP  = 32;

constexpr float WSC   = 16384.0f;         // 1024 bins over [0.46875, 0.53125)
constexpr float WOFF  = -7680.0f;         // -0.46875 * 16384
constexpr float LOG2E = 1.4426950408889634f;
constexpr float FPSCALE  = 67108864.0f;   // 2^26
constexpr float IFPSCALE = 1.4901161193847656e-8f; // 2^-26

__device__ __forceinline__ unsigned u_of_bits(unsigned b) {
    return (b & 0x80000000u) ? ~b : (b | 0x80000000u);
}

__global__ __launch_bounds__(THREADS, 5)
void wdrop_kernel(const float* __restrict__ in, float* __restrict__ out)
{
    __shared__ unsigned hist[NB];                       // 4 KB
    __shared__ unsigned long long histF[NB];            // 8 KB fixed-point exp sums
    __shared__ unsigned long long cand2[C2_CAP];
    __shared__ unsigned m_n;
    __shared__ unsigned s_below;
    __shared__ unsigned long long s_above;              // fixed-point
    __shared__ unsigned long long s_fsum;               // fallback sum
    __shared__ unsigned s_bin, s_rank, s_mode;          // mode: 0 fast 1 slow 2 fallback
    __shared__ float    s_inv;
    __shared__ unsigned long long s_partial;            // suffix+above (excl boundary) fp
    __shared__ unsigned long long s_thr;
    __shared__ unsigned long long s_pref;
    __shared__ unsigned s_rrem;

    const int t    = threadIdx.x;
    const int lane = t & 31;
    const int warp = t >> 5;

    const long long row = blockIdx.x;
    const float4* __restrict__ in4  = reinterpret_cast<const float4*>(in  + row * (long long)N);
    float4*       __restrict__ out4 = reinterpret_cast<float4*>      (out + row * (long long)N);

#pragma unroll
    for (int i = 0; i < NB / THREADS; i++) {
        hist [t + THREADS * i] = 0u;
        histF[t + THREADS * i] = 0ull;
    }
    if (t == 0) { m_n = 0u; s_below = 0u; s_above = 0ull; s_mode = 2u; s_fsum = 0ull; }
    __syncthreads();                       // B1: init

    // ---- pass 1: load, bin, count hist + fixed-point exp sums ----
    float4 xs[VEC];
#pragma unroll
    for (int j = 0; j < VEC; j++) xs[j] = in4[t + THREADS * j];

    unsigned below = 0;
    float aboveF = 0.0f;
#pragma unroll
    for (int j = 0; j < VEC; j++) {
        float vv[4] = {xs[j].x, xs[j].y, xs[j].z, xs[j].w};
#pragma unroll
        for (int c = 0; c < 4; c++) {
            float val = vv[c];
            int b = __float2int_rd(fmaf(val, WSC, WOFF));
            if (b < 0) {
                below++;
            } else {
                float e = exp2f(val * LOG2E);
                if (b < NB) {
                    atomicAdd(&hist[b], 1u);
                    atomicAdd(&histF[b], (unsigned long long)(e * FPSCALE));
                } else {
                    aboveF += e;
                }
            }
        }
    }
#pragma unroll
    for (int o = 16; o; o >>= 1) {
        below  += __shfl_xor_sync(0xffffffffu, below, o);
        aboveF += __shfl_xor_sync(0xffffffffu, aboveF, o);
    }
    if (lane == 0) {
        atomicAdd(&s_below, below);
        atomicAdd(&s_above, (unsigned long long)(aboveF * FPSCALE));
    }
    __syncthreads();                       // B2: hist/partials ready

    // ---- warp 0: scan 1024 bins; compute denominator from histF ----
    if (warp == 0) {
        unsigned sum = 0;
#pragma unroll
        for (int i = 0; i < 32; i++) sum += hist[lane * 32 + i];
        unsigned inc = sum;
#pragma unroll
        for (int o = 1; o < 32; o <<= 1) {
            unsigned nn = __shfl_up_sync(0xffffffffu, inc, o);
            if (lane >= o) inc += nn;
        }
        unsigned c = s_below + inc - sum;
        unsigned lbin = 0, lrank = 0; bool lfound = false;
#pragma unroll
        for (int i = 0; i < 32; i++) {
            unsigned cc = hist[lane * 32 + i];
            if (c <= (unsigned)KDROP && (unsigned)KDROP < c + cc) {
                lbin = (unsigned)(lane * 32 + i);
                lrank = (unsigned)KDROP - c;
                lfound = true;
            }
            c += cc;
        }
        unsigned msk = __ballot_sync(0xffffffffu, lfound);
        if (msk != 0u) {
            int src = __ffs(msk) - 1;
            unsigned bstar = __shfl_sync(0xffffffffu, lbin,  src);
            unsigned rstar = __shfl_sync(0xffffffffu, lrank, src);
            // suffix fixed-point exp sum over bins > bstar (+ bstar if rstar==0)
            unsigned long long fs = 0ull;
#pragma unroll
            for (int i = 0; i < 32; i++) {
                unsigned bb = (unsigned)(lane * 32 + i);
                if (bb > bstar || (bb == bstar && rstar == 0u)) fs += histF[bb];
            }
#pragma unroll
            for (int o = 16; o; o >>= 1)
                fs += __shfl_xor_sync(0xffffffffu, fs, o);
            if (lane == 0) {
                s_bin  = bstar;
                s_rank = rstar;
                if (rstar == 0u) {
                    s_mode = 0u;
                    s_inv  = 1.0f / ((float)(fs + s_above) * IFPSCALE);
                } else {
                    s_mode = 1u;
                    s_partial = fs + s_above;   // excludes boundary bin
                }
            }
        }
    }
    __syncthreads();                       // B3: mode/bstar/inv ready

    unsigned mode  = s_mode;
    const unsigned bstar = s_bin;
    unsigned long long thr = 0ull;

    if (mode == 1u) {
        // ---- slow (~11%): gather boundary-bin keys, rank, exact sum ----
#pragma unroll
        for (int j = 0; j < VEC; j++) {
            float vv[4] = {xs[j].x, xs[j].y, xs[j].z, xs[j].w};
#pragma unroll
            for (int c = 0; c < 4; c++) {
                float val = vv[c];
                int b = __float2int_rd(fmaf(val, WSC, WOFF));
                if ((unsigned)b == bstar) {
                    unsigned p = atomicAdd(&m_n, 1u);
                    if (p < (unsigned)C2_CAP) {
                        unsigned idx = (unsigned)(4 * (t + THREADS * j) + c);
                        cand2[p] = ((unsigned long long)__float_as_uint(val) << 12)
                                 | (unsigned long long)idx;
                    }
                }
            }
        }
        __syncthreads();
        if (warp == 0) {
            unsigned mn = m_n, rstar = s_rank;
            if (mn <= (unsigned)C2_CAP) {
                unsigned long long bsum = 0ull;
                if (lane < mn) {
                    unsigned long long k = cand2[lane];
                    unsigned rk = 0;
                    for (unsigned i = 0; i < mn; i++) rk += (cand2[i] < k) ? 1u : 0u;
                    if (rk == rstar) s_thr = k;
                    if (rk >= rstar) {
                        float v = __uint_as_float((unsigned)(k >> 12));
                        bsum = (unsigned long long)(exp2f(v * LOG2E) * FPSCALE);
                    }
                }
#pragma unroll
                for (int o = 16; o; o >>= 1)
                    bsum += __shfl_xor_sync(0xffffffffu, bsum, o);
                if (lane == 0)
                    s_inv = 1.0f / ((float)(s_partial + bsum) * IFPSCALE);
            } else if (lane == 0) {
                s_mode = 2u;               // overflow -> fallback
            }
        }
        __syncthreads();
        mode = s_mode;
        thr = s_thr;
    }

    // ---- cold exact fallback: radix-select + explicit sum ----
    if (mode == 2u) {
        if (t == 0) { s_pref = 0ull; s_rrem = (unsigned)KDROP; }
        const int shifts[6] = {36, 28, 20, 12, 6, 0};
        const int widths[6] = {256, 256, 256, 256, 64, 64};
        unsigned long long mask = 0ull;
#pragma unroll 1
        for (int L = 0; L < 6; L++) {
            if (t < widths[L]) hist[t] = 0u;
            __syncthreads();
            unsigned long long pref = s_pref;
#pragma unroll 1
            for (int j = 0; j < VEC; j++) {
                float vv[4] = {xs[j].x, xs[j].y, xs[j].z, xs[j].w};
#pragma unroll 1
                for (int c = 0; c < 4; c++) {
                    unsigned idx = (unsigned)(4 * (t + THREADS * j) + c);
                    unsigned long long K =
                        ((unsigned long long)u_of_bits(__float_as_uint(vv[c])) << 12)
                      | (unsigned long long)idx;
                    if ((K & mask) == pref)
                        atomicAdd(&hist[(unsigned)(K >> shifts[L]) & (unsigned)(widths[L] - 1)], 1u);
                }
            }
            __syncthreads();
            if (t == 0) {
                unsigned r = s_rrem, acc = 0;
                for (int i = 0; i < widths[L]; i++) {
                    unsigned cc = hist[i];
                    if (acc <= r && r < acc + cc) {
                        s_pref = pref | ((unsigned long long)i << shifts[L]);
                        s_rrem = r - acc;
                        break;
                    }
                    acc += cc;
                }
            }
            mask |= (unsigned long long)(widths[L] - 1) << shifts[L];
            __syncthreads();
        }
        if (t == 0) {
            unsigned long long pref = s_pref;
            unsigned uu = (unsigned)(pref >> 12);
            unsigned bits = (uu & 0x80000000u) ? (uu ^ 0x80000000u) : ~uu;
            s_thr = ((unsigned long long)bits << 12) | (pref & 0xFFFull);
        }
        __syncthreads();
        thr = s_thr;
        // explicit kept-exp sum (fixed point, deterministic)
        {
            const float    tv = __uint_as_float((unsigned)(thr >> 12));
            const unsigned ti = (unsigned)(thr & 0xFFFull);
            float ls = 0.0f;
#pragma unroll 1
            for (int j = 0; j < VEC; j++) {
                float vv[4] = {xs[j].x, xs[j].y, xs[j].z, xs[j].w};
#pragma unroll 1
                for (int c = 0; c < 4; c++) {
                    float val = vv[c];
                    unsigned idx = (unsigned)(4 * (t + THREADS * j) + c);
                    if ((val > tv) || (val == tv && idx >= ti))
                        ls += exp2f(val * LOG2E);
                }
            }
#pragma unroll
            for (int o = 16; o; o >>= 1) ls += __shfl_xor_sync(0xffffffffu, ls, o);
            if (lane == 0) atomicAdd(&s_fsum, (unsigned long long)(ls * FPSCALE));
            __syncthreads();
            if (t == 0) s_inv = 1.0f / ((float)s_fsum * IFPSCALE);
            __syncthreads();
        }
    }

    const float inv = s_inv;

    // ---- pass 3: keep + exp2 + scaled store ----
    if (mode == 0u) {
        const int bs = (int)bstar;
#pragma unroll
        for (int j = 0; j < VEC; j++) {
            float vv[4] = {xs[j].x, xs[j].y, xs[j].z, xs[j].w};
            float oo[4];
#pragma unroll
            for (int c = 0; c < 4; c++) {
                float val = vv[c];
                int b = __float2int_rd(fmaf(val, WSC, WOFF));
                oo[c] = (b >= bs) ? exp2f(val * LOG2E) * inv : 0.0f;
            }
            float4 o4 = {oo[0], oo[1], oo[2], oo[3]};
            out4[t + THREADS * j] = o4;
        }
    } else {
        const float    tv = __uint_as_float((unsigned)(thr >> 12));
        const unsigned ti = (unsigned)(thr & 0xFFFull);
#pragma unroll
        for (int j = 0; j < VEC; j++) {
            float vv[4] = {xs[j].x, xs[j].y, xs[j].z, xs[j].w};
            float oo[4];
#pragma unroll
            for (int c = 0; c < 4; c++) {
                float val = vv[c];
                unsigned idx = (unsigned)(4 * (t + THREADS * j) + c);
                bool keep = (val > tv) || (val == tv && idx >= ti);
                oo[c] = keep ? exp2f(val * LOG2E) * inv : 0.0f;
            }
            float4 o4 = {oo[0], oo[1], oo[2], oo[3]};
            out4[t + THREADS * j] = o4;
        }
    }
}

} // anonymous namespace

extern "C" void kernel_launch(void* const* d_in, const int* in_sizes, int n_in,
                              void* d_out, int out_size)
{
    (void)n_in; (void)in_sizes;
    const float* w = (const float*)d_in[0];
    float* outp = (float*)d_out;
    int rows = out_size / N;            // 8192
    wdrop_kernel<<<rows, THREADS>>>(w, outp);
}

// round 10
// speedup vs baseline: 1.9546x; 1.9546x over previous
#include <cuda_runtime.h>
#include <cuda_bf16.h>
#include <stdint.h>

// WeightsDropout: per row of [8192,1,4096] f32, zero the 2048 smallest
// (stable-argsort tie-break by index), softmax over survivors.
//
// Champion (92.3us) structure, minus the max pass (vals in (0,1): exp(val)
// cannot overflow; softmax is shift-invariant) and with the below-count
// fused into the bin computation (one FFMA+F2I per element).
//
// One CTA (512 thr) per row; row in registers (2 float4/thread).
// 256-bin histogram over [0.375, 0.625) + count(b<0); scan finds the
// rank-2048 bin; gather that bin's few keys (bits<<12|idx == stable-sort
// order); warp 0 picks the key with in-bin rank rstar -> exact threshold.
// Hot path: single (val,idx) compare + __expf. Fallback: full-range
// 256-bin re-histogram (same machinery, still exact via key ranking).

namespace {

constexpr int N        = 4096;
constexpr int KDROP    = 2048;
constexpr int THREADS  = 512;
constexpr int VEC      = N / 4 / THREADS;   // 2 float4 per thread
constexpr int NWARP    = THREADS / 32;      // 16
constexpr int NB       = 256;
constexpr int CAND_CAP = 256;

constexpr float WSC  = 1024.0f;             // 256 bins over [0.375, 0.625)
constexpr float WOFF = -384.0f;             // -0.375 * 1024

__global__ __launch_bounds__(THREADS, 3)
void wdrop_kernel(const float* __restrict__ in, float* __restrict__ out)
{
    __shared__ unsigned hist[NB];
    __shared__ unsigned long long cand[CAND_CAP];
    __shared__ unsigned cand_n;
    __shared__ float    s_redf[NWARP];
    __shared__ unsigned s_redu[NWARP];
    __shared__ unsigned s_bin, s_rank, s_found;
    __shared__ float    s_inv;
    __shared__ unsigned long long s_thr;

    const int t    = threadIdx.x;
    const int lane = t & 31;
    const int warp = t >> 5;

    const long long row = blockIdx.x;
    const float4* __restrict__ in4  = reinterpret_cast<const float4*>(in  + row * (long long)N);
    float4*       __restrict__ out4 = reinterpret_cast<float4*>      (out + row * (long long)N);

    if (t < NB) hist[t] = 0u;
    if (t == 0) { cand_n = 0u; s_found = 0u; }
    __syncthreads();

    // ---- pass 1: load into registers; below-count + window histogram ----
    float4 xs[VEC];
#pragma unroll
    for (int j = 0; j < VEC; j++) xs[j] = in4[t + THREADS * j];

    unsigned below = 0;
#pragma unroll
    for (int j = 0; j < VEC; j++) {
        float vv[4] = {xs[j].x, xs[j].y, xs[j].z, xs[j].w};
#pragma unroll
        for (int c = 0; c < 4; c++) {
            int b = __float2int_rd(fmaf(vv[c], WSC, WOFF));
            below += (b < 0) ? 1u : 0u;
            if ((unsigned)b < (unsigned)NB) atomicAdd(&hist[b], 1u);
        }
    }
#pragma unroll
    for (int o = 16; o; o >>= 1)
        below += __shfl_xor_sync(0xffffffffu, below, o);
    if (lane == 0) s_redu[warp] = below;
    __syncthreads();

    // ---- warp 0: combine below; scan histogram for rank-KDROP bin ----
    if (warp == 0) {
        unsigned b = (lane < NWARP) ? s_redu[lane] : 0u;
#pragma unroll
        for (int o = 16; o; o >>= 1)
            b += __shfl_xor_sync(0xffffffffu, b, o);

        unsigned c8[8]; unsigned sum = 0;
#pragma unroll
        for (int i = 0; i < 8; i++) { c8[i] = hist[lane * 8 + i]; sum += c8[i]; }
        unsigned inc = sum;
#pragma unroll
        for (int o = 1; o < 32; o <<= 1) {
            unsigned nn = __shfl_up_sync(0xffffffffu, inc, o);
            if (lane >= o) inc += nn;
        }
        unsigned c = b + inc - sum;
#pragma unroll
        for (int i = 0; i < 8; i++) {
            unsigned cc = c8[i];
            if (c <= (unsigned)KDROP && (unsigned)KDROP < c + cc) {
                s_bin = (unsigned)(lane * 8 + i);
                s_rank = (unsigned)KDROP - c;
                s_found = 1u;
            }
            c += cc;
        }
    }
    __syncthreads();

    // ---- fallback: boundary outside window (ultra-rare, still exact) ----
    float sc = WSC, off = WOFF;
    if (!s_found) {
        if (t < NB) hist[t] = 0u;
        __syncthreads();
#pragma unroll
        for (int j = 0; j < VEC; j++) {
            float vv[4] = {xs[j].x, xs[j].y, xs[j].z, xs[j].w};
#pragma unroll
            for (int c = 0; c < 4; c++) {
                int b = __float2int_rd(vv[c] * 256.0f);
                b = max(min(b, NB - 1), 0);
                atomicAdd(&hist[b], 1u);
            }
        }
        __syncthreads();
        if (warp == 0) {
            unsigned c8[8]; unsigned sum = 0;
#pragma unroll
            for (int i = 0; i < 8; i++) { c8[i] = hist[lane * 8 + i]; sum += c8[i]; }
            unsigned inc = sum;
#pragma unroll
            for (int o = 1; o < 32; o <<= 1) {
                unsigned nn = __shfl_up_sync(0xffffffffu, inc, o);
                if (lane >= o) inc += nn;
            }
            unsigned c = inc - sum;
#pragma unroll
            for (int i = 0; i < 8; i++) {
                unsigned cc = c8[i];
                if (c <= (unsigned)KDROP && (unsigned)KDROP < c + cc) {
                    s_bin = (unsigned)(lane * 8 + i);
                    s_rank = (unsigned)KDROP - c;
                }
                c += cc;
            }
        }
        sc = 256.0f; off = 0.0f;
        __syncthreads();
    }

    const unsigned bstar = s_bin;
    const unsigned rstar = s_rank;

    // ---- gather boundary-bin candidates (keys) ----
#pragma unroll
    for (int j = 0; j < VEC; j++) {
        float vv[4] = {xs[j].x, xs[j].y, xs[j].z, xs[j].w};
#pragma unroll
        for (int c = 0; c < 4; c++) {
            float val = vv[c];
            int b = __float2int_rd(fmaf(val, sc, off));
            b = min(b, NB - 1);                       // clamp matches fallback binning
            if ((unsigned)b == bstar) {
                unsigned p = atomicAdd(&cand_n, 1u);
                if (p < (unsigned)CAND_CAP) {
                    unsigned idx = (unsigned)(4 * (t + THREADS * j) + c);
                    cand[p] = ((unsigned long long)__float_as_uint(val) << 12)
                            | (unsigned long long)idx;
                }
            }
        }
    }
    __syncthreads();

    // ---- warp 0: threshold key = candidate with in-bin rank rstar ----
    if (warp == 0) {
        unsigned c = min(cand_n, (unsigned)CAND_CAP);
        for (unsigned base = 0; base < c; base += 32) {
            unsigned q = base + lane;
            if (q < c) {
                unsigned long long k = cand[q];
                unsigned rk = 0;
                for (unsigned i = 0; i < c; i++) rk += (cand[i] < k) ? 1u : 0u;
                if (rk == rstar) s_thr = k;           // global rank == KDROP
            }
        }
    }
    __syncthreads();

    const unsigned long long thr = s_thr;
    const float    thr_val = __uint_as_float((unsigned)(thr >> 12));
    const unsigned thr_idx = (unsigned)(thr & 0xFFFull);

    // ---- hot path: single-compare keep, exp, sum ----
    float lsum = 0.0f;
#pragma unroll
    for (int j = 0; j < VEC; j++) {
        float vv[4] = {xs[j].x, xs[j].y, xs[j].z, xs[j].w};
        float ee[4];
#pragma unroll
        for (int c = 0; c < 4; c++) {
            float val = vv[c];
            unsigned idx = (unsigned)(4 * (t + THREADS * j) + c);
            bool keep = (val > thr_val) || (val == thr_val && idx >= thr_idx);
            float e = keep ? __expf(val) : 0.0f;      // no max: vals in (0,1)
            ee[c] = e;
            lsum += e;
        }
        xs[j].x = ee[0]; xs[j].y = ee[1]; xs[j].z = ee[2]; xs[j].w = ee[3];
    }
#pragma unroll
    for (int o = 16; o; o >>= 1) lsum += __shfl_xor_sync(0xffffffffu, lsum, o);
    if (lane == 0) s_redf[warp] = lsum;
    __syncthreads();
    if (warp == 0) {
        float s = (lane < NWARP) ? s_redf[lane] : 0.0f;
#pragma unroll
        for (int o = 16; o; o >>= 1) s += __shfl_xor_sync(0xffffffffu, s, o);
        if (lane == 0) s_inv = 1.0f / s;
    }
    __syncthreads();
    const float inv = s_inv;

    // ---- scaled store straight from registers ----
#pragma unroll
    for (int j = 0; j < VEC; j++) {
        float4 o4 = {xs[j].x * inv, xs[j].y * inv, xs[j].z * inv, xs[j].w * inv};
        out4[t + THREADS * j] = o4;
    }
}

} // anonymous namespace

extern "C" void kernel_launch(void* const* d_in, const int* in_sizes, int n_in,
                              void* d_out, int out_size)
{
    (void)n_in; (void)in_sizes;
    const float* w = (const float*)d_in[0];
    float* outp = (float*)d_out;
    int rows = out_size / N;            // 8192
    wdrop_kernel<<<rows, THREADS>>>(w, outp);
}

// round 11
// speedup vs baseline: 2.0044x; 1.0255x over previous
#include <cuda_runtime.h>
#include <cuda_bf16.h>
#include <stdint.h>

// WeightsDropout: per row of [8192,1,4096] f32, zero the 2048 smallest
// (stable-argsort tie-break by index), softmax over survivors.
//
// Champion chassis (R10, 82.4us): one CTA (512 thr) per row, row in
// registers, 256-bin window histogram over [0.375,0.625) + below-count,
// warp-0 scan -> boundary bin, gather its keys (bits<<12|idx == stable
// order), warp-0 rank -> exact threshold key.
// New: (a) warp 0 detects whether any DROPPED candidate shares thr_val;
// if not (P ~ 1-5e-4), pass-3 keep is a single `val >= thr_val` compare
// (no idx math). (b) gather uses exact float bin bounds (2 FSETPs).

namespace {

constexpr int N        = 4096;
constexpr int KDROP    = 2048;
constexpr int THREADS  = 512;
constexpr int VEC      = N / 4 / THREADS;   // 2 float4 per thread
constexpr int NWARP    = THREADS / 32;      // 16
constexpr int NB       = 256;
constexpr int CAND_CAP = 256;

constexpr float WSC  = 1024.0f;             // 256 bins over [0.375, 0.625)
constexpr float WOFF = -384.0f;             // -0.375 * 1024

__global__ __launch_bounds__(THREADS, 3)
void wdrop_kernel(const float* __restrict__ in, float* __restrict__ out)
{
    __shared__ unsigned hist[NB];
    __shared__ unsigned long long cand[CAND_CAP];
    __shared__ unsigned cand_n;
    __shared__ float    s_redf[NWARP];
    __shared__ unsigned s_redu[NWARP];
    __shared__ unsigned s_bin, s_rank, s_found, s_tie;
    __shared__ float    s_inv;
    __shared__ unsigned long long s_thr;

    const int t    = threadIdx.x;
    const int lane = t & 31;
    const int warp = t >> 5;

    const long long row = blockIdx.x;
    const float4* __restrict__ in4  = reinterpret_cast<const float4*>(in  + row * (long long)N);
    float4*       __restrict__ out4 = reinterpret_cast<float4*>      (out + row * (long long)N);

    if (t < NB) hist[t] = 0u;
    if (t == 0) { cand_n = 0u; s_found = 0u; s_tie = 0u; }
    __syncthreads();

    // ---- pass 1: load into registers; below-count + window histogram ----
    float4 xs[VEC];
#pragma unroll
    for (int j = 0; j < VEC; j++) xs[j] = in4[t + THREADS * j];

    unsigned below = 0;
#pragma unroll
    for (int j = 0; j < VEC; j++) {
        float vv[4] = {xs[j].x, xs[j].y, xs[j].z, xs[j].w};
#pragma unroll
        for (int c = 0; c < 4; c++) {
            int b = __float2int_rd(fmaf(vv[c], WSC, WOFF));
            below += (b < 0) ? 1u : 0u;
            if ((unsigned)b < (unsigned)NB) atomicAdd(&hist[b], 1u);
        }
    }
#pragma unroll
    for (int o = 16; o; o >>= 1)
        below += __shfl_xor_sync(0xffffffffu, below, o);
    if (lane == 0) s_redu[warp] = below;
    __syncthreads();

    // ---- warp 0: combine below; scan histogram for rank-KDROP bin ----
    if (warp == 0) {
        unsigned b = (lane < NWARP) ? s_redu[lane] : 0u;
#pragma unroll
        for (int o = 16; o; o >>= 1)
            b += __shfl_xor_sync(0xffffffffu, b, o);

        unsigned c8[8]; unsigned sum = 0;
#pragma unroll
        for (int i = 0; i < 8; i++) { c8[i] = hist[lane * 8 + i]; sum += c8[i]; }
        unsigned inc = sum;
#pragma unroll
        for (int o = 1; o < 32; o <<= 1) {
            unsigned nn = __shfl_up_sync(0xffffffffu, inc, o);
            if (lane >= o) inc += nn;
        }
        unsigned c = b + inc - sum;
#pragma unroll
        for (int i = 0; i < 8; i++) {
            unsigned cc = c8[i];
            if (c <= (unsigned)KDROP && (unsigned)KDROP < c + cc) {
                s_bin = (unsigned)(lane * 8 + i);
                s_rank = (unsigned)KDROP - c;
                s_found = 1u;
            }
            c += cc;
        }
    }
    __syncthreads();

    // ---- fallback: boundary outside window (ultra-rare, still exact) ----
    bool fb = !s_found;
    if (fb) {
        if (t < NB) hist[t] = 0u;
        __syncthreads();
#pragma unroll
        for (int j = 0; j < VEC; j++) {
            float vv[4] = {xs[j].x, xs[j].y, xs[j].z, xs[j].w};
#pragma unroll
            for (int c = 0; c < 4; c++) {
                int b = __float2int_rd(vv[c] * 256.0f);
                b = max(min(b, NB - 1), 0);
                atomicAdd(&hist[b], 1u);
            }
        }
        __syncthreads();
        if (warp == 0) {
            unsigned c8[8]; unsigned sum = 0;
#pragma unroll
            for (int i = 0; i < 8; i++) { c8[i] = hist[lane * 8 + i]; sum += c8[i]; }
            unsigned inc = sum;
#pragma unroll
            for (int o = 1; o < 32; o <<= 1) {
                unsigned nn = __shfl_up_sync(0xffffffffu, inc, o);
                if (lane >= o) inc += nn;
            }
            unsigned c = inc - sum;
#pragma unroll
            for (int i = 0; i < 8; i++) {
                unsigned cc = c8[i];
                if (c <= (unsigned)KDROP && (unsigned)KDROP < c + cc) {
                    s_bin = (unsigned)(lane * 8 + i);
                    s_rank = (unsigned)KDROP - c;
                }
                c += cc;
            }
        }
        __syncthreads();
    }

    const unsigned bstar = s_bin;
    const unsigned rstar = s_rank;

    // exact float bounds of the boundary bin (divides by powers of two)
    float blo, bhi;
    if (!fb) {
        blo = (float)(bstar + 384u) * (1.0f / 1024.0f);
        bhi = (float)(bstar + 385u) * (1.0f / 1024.0f);
    } else {
        blo = (bstar == 0u)        ? -3.4e38f : (float)bstar        * (1.0f / 256.0f);
        bhi = (bstar == NB - 1u)   ?  3.4e38f : (float)(bstar + 1u) * (1.0f / 256.0f);
    }

    // ---- gather boundary-bin candidates (two FSETPs per element) ----
#pragma unroll
    for (int j = 0; j < VEC; j++) {
        float vv[4] = {xs[j].x, xs[j].y, xs[j].z, xs[j].w};
#pragma unroll
        for (int c = 0; c < 4; c++) {
            float val = vv[c];
            if (val >= blo && val < bhi) {
                unsigned p = atomicAdd(&cand_n, 1u);
                if (p < (unsigned)CAND_CAP) {
                    unsigned idx = (unsigned)(4 * (t + THREADS * j) + c);
                    cand[p] = ((unsigned long long)__float_as_uint(val) << 12)
                            | (unsigned long long)idx;
                }
            }
        }
    }
    __syncthreads();

    // ---- warp 0: threshold key + tie detection ----
    if (warp == 0) {
        unsigned c = min(cand_n, (unsigned)CAND_CAP);
        unsigned long long thr_loc = 0ull;
        // find threshold key (rank == rstar within the bin)
        for (unsigned base = 0; base < c; base += 32) {
            unsigned q = base + lane;
            bool hit = false;
            unsigned long long k = 0ull;
            if (q < c) {
                k = cand[q];
                unsigned rk = 0;
                for (unsigned i = 0; i < c; i++) rk += (cand[i] < k) ? 1u : 0u;
                hit = (rk == rstar);
            }
            unsigned msk = __ballot_sync(0xffffffffu, hit);
            if (msk) thr_loc = __shfl_sync(0xffffffffu, k, __ffs(msk) - 1);
        }
        if (lane == 0) s_thr = thr_loc;
        // tie: some DROPPED candidate shares thr's value bits
        unsigned thr_bits = (unsigned)(thr_loc >> 12);
        bool tie = false;
        for (unsigned q = lane; q < c; q += 32) {
            unsigned long long k = cand[q];
            if (k < thr_loc && (unsigned)(k >> 12) == thr_bits) tie = true;
        }
        if (__ballot_sync(0xffffffffu, tie) && lane == 0) s_tie = 1u;
    }
    __syncthreads();

    const unsigned long long thr = s_thr;
    const float    thr_val = __uint_as_float((unsigned)(thr >> 12));
    const unsigned tie     = s_tie;

    // ---- hot path: keep + exp + sum ----
    float lsum = 0.0f;
    if (!tie) {
        // no dropped element equals thr_val -> keep iff val >= thr_val
#pragma unroll
        for (int j = 0; j < VEC; j++) {
            float vv[4] = {xs[j].x, xs[j].y, xs[j].z, xs[j].w};
            float ee[4];
#pragma unroll
            for (int c = 0; c < 4; c++) {
                float val = vv[c];
                float e = (val >= thr_val) ? __expf(val) : 0.0f;
                ee[c] = e;
                lsum += e;
            }
            xs[j].x = ee[0]; xs[j].y = ee[1]; xs[j].z = ee[2]; xs[j].w = ee[3];
        }
    } else {
        const unsigned thr_idx = (unsigned)(thr & 0xFFFull);
#pragma unroll
        for (int j = 0; j < VEC; j++) {
            float vv[4] = {xs[j].x, xs[j].y, xs[j].z, xs[j].w};
            float ee[4];
#pragma unroll
            for (int c = 0; c < 4; c++) {
                float val = vv[c];
                unsigned idx = (unsigned)(4 * (t + THREADS * j) + c);
                bool keep = (val > thr_val) || (val == thr_val && idx >= thr_idx);
                float e = keep ? __expf(val) : 0.0f;
                ee[c] = e;
                lsum += e;
            }
            xs[j].x = ee[0]; xs[j].y = ee[1]; xs[j].z = ee[2]; xs[j].w = ee[3];
        }
    }
#pragma unroll
    for (int o = 16; o; o >>= 1) lsum += __shfl_xor_sync(0xffffffffu, lsum, o);
    if (lane == 0) s_redf[warp] = lsum;
    __syncthreads();
    if (warp == 0) {
        float s = (lane < NWARP) ? s_redf[lane] : 0.0f;
#pragma unroll
        for (int o = 16; o; o >>= 1) s += __shfl_xor_sync(0xffffffffu, s, o);
        if (lane == 0) s_inv = 1.0f / s;
    }
    __syncthreads();
    const float inv = s_inv;

    // ---- scaled store straight from registers ----
#pragma unroll
    for (int j = 0; j < VEC; j++) {
        float4 o4 = {xs[j].x * inv, xs[j].y * inv, xs[j].z * inv, xs[j].w * inv};
        out4[t + THREADS * j] = o4;
    }
}

} // anonymous namespace

extern "C" void kernel_launch(void* const* d_in, const int* in_sizes, int n_in,
                              void* d_out, int out_size)
{
    (void)n_in; (void)in_sizes;
    const float* w = (const float*)d_in[0];
    float* outp = (float*)d_out;
    int rows = out_size / N;            // 8192
    wdrop_kernel<<<rows, THREADS>>>(w, outp);
}